// round 2
// baseline (speedup 1.0000x reference)
#include <cuda_runtime.h>

// LSTMModel: 2-layer LSTM (H=50), B=2048, T=512, input dim 1.
// Fused persistent kernel, one CTA per 16-batch tile, both layers per timestep.
// Matmuls use packed fma.rn.f32x2 (FFMA2) with k-pair packing: h-pairs come
// pre-packed from LDS.64 of adjacent hc columns; W stored k-major per gate.

#define Hh 50
#define G4 200          // 4*H
#define GP 224          // padded gate dim (56 quads of 4)
#define KP0 52          // W0 row stride (k-major, 50 -> 52)
#define KP1 100         // W1 row stride (k-major, K=100)
#define BT 16           // batch tile per CTA
#define NT 224          // threads per CTA (4 b-groups x 56 g-quads)
#define TT 512          // timesteps
#define HCS 104         // hc row stride: cols 0..49 h0, 50..99 h1, pad

typedef unsigned long long ull;

// shared layout (floats)
#define SM_W0    0
#define SM_W1    (SM_W0 + GP*KP0)        // 224*52  = 11648
#define SM_GATES (SM_W1 + GP*KP1)        // 224*100 = 22400
#define SM_HC    (SM_GATES + BT*GP)      // 3584
#define SM_B0    (SM_HC + BT*HCS)        // 1664
#define SM_B1    (SM_B0 + GP)
#define SM_WIH0  (SM_B1 + GP)
#define SM_FLOATS (SM_WIH0 + GP)
#define SMEM_BYTES (SM_FLOATS * sizeof(float))

__device__ __forceinline__ void ffma2(ull& d, ull a, ull b) {
    asm("fma.rn.f32x2 %0, %1, %2, %0;" : "+l"(d) : "l"(a), "l"(b));
}
__device__ __forceinline__ void unpack2(ull v, float& lo, float& hi) {
    asm("mov.b64 {%0, %1}, %2;" : "=f"(lo), "=f"(hi) : "l"(v));
}

__device__ __forceinline__ float sigf(float x) {
    float e = __expf(-x);
    return __fdividef(1.0f, 1.0f + e);
}
__device__ __forceinline__ float tanhf_fast(float x) {
    float e = __expf(2.0f * x);
    return 1.0f - __fdividef(2.0f, e + 1.0f);
}

__global__ __launch_bounds__(NT, 1)
void lstm2_kernel(const float* __restrict__ x,
                  const float* __restrict__ W_ih0, const float* __restrict__ W_hh0,
                  const float* __restrict__ b_ih0, const float* __restrict__ b_hh0,
                  const float* __restrict__ W_ih1, const float* __restrict__ W_hh1,
                  const float* __restrict__ b_ih1, const float* __restrict__ b_hh1,
                  const float* __restrict__ W_fc,  const float* __restrict__ b_fc,
                  float* __restrict__ out)
{
    extern __shared__ float sm[];
    float* W0    = sm + SM_W0;     // [GP][KP0] k-major
    float* W1    = sm + SM_W1;     // [GP][KP1] k-major
    float* gates = sm + SM_GATES;  // [BT][GP]
    float* hc    = sm + SM_HC;     // [BT][HCS]
    float* bias0 = sm + SM_B0;
    float* bias1 = sm + SM_B1;
    float* wih0  = sm + SM_WIH0;

    const int tid = threadIdx.x;

    // ---- one-time: weights into shared, k-major (native layout of W_hh) ----
    for (int i = tid; i < GP * KP0; i += NT) {
        int g = i / KP0, k = i - g * KP0;
        W0[i] = (g < G4 && k < Hh) ? W_hh0[g * Hh + k] : 0.0f;
    }
    for (int i = tid; i < GP * KP1; i += NT) {
        int g = i / KP1, k = i - g * KP1;
        float v = 0.0f;
        if (g < G4) v = (k < Hh) ? W_ih1[g * Hh + k] : W_hh1[g * Hh + (k - Hh)];
        W1[i] = v;
    }
    for (int g = tid; g < GP; g += NT) {
        bias0[g] = (g < G4) ? (b_ih0[g] + b_hh0[g]) : 0.0f;
        bias1[g] = (g < G4) ? (b_ih1[g] + b_hh1[g]) : 0.0f;
        wih0[g]  = (g < G4) ? W_ih0[g] : 0.0f;
    }
    for (int i = tid; i < BT * HCS; i += NT) hc[i] = 0.0f;
    __syncthreads();

    // ---- thread tiling: 4 b's x 4 consecutive g's ----
    const int bg = tid / 56;          // 0..3
    const int q  = tid - bg * 56;     // 0..55
    const int g0 = q * 4;
    const int bbase = bg * 4;

    const float* hb0 = hc + (bbase + 0) * HCS;
    const float* hb1 = hc + (bbase + 1) * HCS;
    const float* hb2 = hc + (bbase + 2) * HCS;
    const float* hb3 = hc + (bbase + 3) * HCS;

    float c0r[4] = {0.f, 0.f, 0.f, 0.f};
    float c1r[4] = {0.f, 0.f, 0.f, 0.f};

    const float* xrow = x + (size_t)(blockIdx.x) * BT * TT;

    const float bv00 = bias0[g0], bv01 = bias0[g0+1], bv02 = bias0[g0+2], bv03 = bias0[g0+3];
    const float bv10 = bias1[g0], bv11 = bias1[g0+1], bv12 = bias1[g0+2], bv13 = bias1[g0+3];
    const float wi0 = wih0[g0], wi1 = wih0[g0+1], wi2 = wih0[g0+2], wi3 = wih0[g0+3];

    const float* w0r = W0 + g0 * KP0;
    const float* w1r = W1 + g0 * KP1;

    for (int t = 0; t < TT; ++t) {
        // ===== matmul A: gates0 = bias0 + x*W_ih0 + h0 @ W_hh0^T  (K=50) =====
        ull a[4][4];
        #pragma unroll
        for (int bb = 0; bb < 4; ++bb)
            #pragma unroll
            for (int gg = 0; gg < 4; ++gg) a[bb][gg] = 0ull;

        #pragma unroll 4
        for (int kc = 0; kc < 48; kc += 4) {
            ull w[4][2];
            #pragma unroll
            for (int gg = 0; gg < 4; ++gg) {
                ulonglong2 wv = *(const ulonglong2*)(w0r + gg * KP0 + kc);
                w[gg][0] = wv.x; w[gg][1] = wv.y;
            }
            ull h[4][2];
            h[0][0] = *(const ull*)(hb0 + kc); h[0][1] = *(const ull*)(hb0 + kc + 2);
            h[1][0] = *(const ull*)(hb1 + kc); h[1][1] = *(const ull*)(hb1 + kc + 2);
            h[2][0] = *(const ull*)(hb2 + kc); h[2][1] = *(const ull*)(hb2 + kc + 2);
            h[3][0] = *(const ull*)(hb3 + kc); h[3][1] = *(const ull*)(hb3 + kc + 2);
            #pragma unroll
            for (int bb = 0; bb < 4; ++bb)
                #pragma unroll
                for (int gg = 0; gg < 4; ++gg) {
                    ffma2(a[bb][gg], w[gg][0], h[bb][0]);
                    ffma2(a[bb][gg], w[gg][1], h[bb][1]);
                }
        }
        {   // remainder k = 48,49
            ull w[4];
            #pragma unroll
            for (int gg = 0; gg < 4; ++gg) w[gg] = *(const ull*)(w0r + gg * KP0 + 48);
            ull h[4];
            h[0] = *(const ull*)(hb0 + 48); h[1] = *(const ull*)(hb1 + 48);
            h[2] = *(const ull*)(hb2 + 48); h[3] = *(const ull*)(hb3 + 48);
            #pragma unroll
            for (int bb = 0; bb < 4; ++bb)
                #pragma unroll
                for (int gg = 0; gg < 4; ++gg) ffma2(a[bb][gg], w[gg], h[bb]);
        }
        {
            float xv[4];
            xv[0] = __ldg(xrow + (bbase + 0) * TT + t);
            xv[1] = __ldg(xrow + (bbase + 1) * TT + t);
            xv[2] = __ldg(xrow + (bbase + 2) * TT + t);
            xv[3] = __ldg(xrow + (bbase + 3) * TT + t);
            const float bia[4] = {bv00, bv01, bv02, bv03};
            const float wiv[4] = {wi0, wi1, wi2, wi3};
            #pragma unroll
            for (int bb = 0; bb < 4; ++bb) {
                float v[4];
                #pragma unroll
                for (int gg = 0; gg < 4; ++gg) {
                    float lo, hi; unpack2(a[bb][gg], lo, hi);
                    v[gg] = fmaf(xv[bb], wiv[gg], bia[gg]) + (lo + hi);
                }
                *(float4*)(gates + (bbase + bb) * GP + g0) = make_float4(v[0], v[1], v[2], v[3]);
            }
        }
        __syncthreads();

        // ===== nonlinearity layer 0 -> h0 (hc cols 0..49) =====
        #pragma unroll
        for (int r = 0; r < 4; ++r) {
            int p = tid + r * NT;
            if (p < BT * Hh) {
                int b = p / Hh, j = p - b * Hh;
                const float* gb = gates + b * GP;
                float iv = sigf(gb[j]);
                float fv = sigf(gb[j + Hh]);
                float gv = tanhf_fast(gb[j + 2 * Hh]);
                float ov = sigf(gb[j + 3 * Hh]);
                float c = fmaf(fv, c0r[r], iv * gv);
                c0r[r] = c;
                hc[b * HCS + j] = ov * tanhf_fast(c);
            }
        }
        __syncthreads();

        // ===== matmul B: gates1 = bias1 + [h0;h1] @ [W_ih1;W_hh1]^T  (K=100) =====
        ull bacc[4][4];
        #pragma unroll
        for (int bb = 0; bb < 4; ++bb)
            #pragma unroll
            for (int gg = 0; gg < 4; ++gg) bacc[bb][gg] = 0ull;

        #pragma unroll 5
        for (int kc = 0; kc < 100; kc += 4) {
            ull w[4][2];
            #pragma unroll
            for (int gg = 0; gg < 4; ++gg) {
                ulonglong2 wv = *(const ulonglong2*)(w1r + gg * KP1 + kc);
                w[gg][0] = wv.x; w[gg][1] = wv.y;
            }
            ull h[4][2];
            h[0][0] = *(const ull*)(hb0 + kc); h[0][1] = *(const ull*)(hb0 + kc + 2);
            h[1][0] = *(const ull*)(hb1 + kc); h[1][1] = *(const ull*)(hb1 + kc + 2);
            h[2][0] = *(const ull*)(hb2 + kc); h[2][1] = *(const ull*)(hb2 + kc + 2);
            h[3][0] = *(const ull*)(hb3 + kc); h[3][1] = *(const ull*)(hb3 + kc + 2);
            #pragma unroll
            for (int bb = 0; bb < 4; ++bb)
                #pragma unroll
                for (int gg = 0; gg < 4; ++gg) {
                    ffma2(bacc[bb][gg], w[gg][0], h[bb][0]);
                    ffma2(bacc[bb][gg], w[gg][1], h[bb][1]);
                }
        }
        {
            const float bia[4] = {bv10, bv11, bv12, bv13};
            #pragma unroll
            for (int bb = 0; bb < 4; ++bb) {
                float v[4];
                #pragma unroll
                for (int gg = 0; gg < 4; ++gg) {
                    float lo, hi; unpack2(bacc[bb][gg], lo, hi);
                    v[gg] = bia[gg] + (lo + hi);
                }
                *(float4*)(gates + (bbase + bb) * GP + g0) = make_float4(v[0], v[1], v[2], v[3]);
            }
        }
        __syncthreads();

        // ===== nonlinearity layer 1 -> h1 (hc cols 50..99) =====
        #pragma unroll
        for (int r = 0; r < 4; ++r) {
            int p = tid + r * NT;
            if (p < BT * Hh) {
                int b = p / Hh, j = p - b * Hh;
                const float* gb = gates + b * GP;
                float iv = sigf(gb[j]);
                float fv = sigf(gb[j + Hh]);
                float gv = tanhf_fast(gb[j + 2 * Hh]);
                float ov = sigf(gb[j + 3 * Hh]);
                float c = fmaf(fv, c1r[r], iv * gv);
                c1r[r] = c;
                hc[b * HCS + Hh + j] = ov * tanhf_fast(c);
            }
        }
        __syncthreads();
    }

    // ===== final FC: out[b] = h1[b] . W_fc + b_fc =====
    if (tid < BT) {
        float s = b_fc[0];
        const float* hrow = hc + tid * HCS + Hh;
        #pragma unroll
        for (int j = 0; j < Hh; ++j) s = fmaf(hrow[j], __ldg(W_fc + j), s);
        out[blockIdx.x * BT + tid] = s;
    }
}

extern "C" void kernel_launch(void* const* d_in, const int* in_sizes, int n_in,
                              void* d_out, int out_size)
{
    const float* x     = (const float*)d_in[0];
    const float* W_ih0 = (const float*)d_in[1];
    const float* W_hh0 = (const float*)d_in[2];
    const float* b_ih0 = (const float*)d_in[3];
    const float* b_hh0 = (const float*)d_in[4];
    const float* W_ih1 = (const float*)d_in[5];
    const float* W_hh1 = (const float*)d_in[6];
    const float* b_ih1 = (const float*)d_in[7];
    const float* b_hh1 = (const float*)d_in[8];
    const float* W_fc  = (const float*)d_in[9];
    const float* b_fc  = (const float*)d_in[10];
    float* out = (float*)d_out;

    int B = in_sizes[0] / TT;          // x is [B, T, 1]
    int grid = B / BT;                 // 2048/16 = 128 CTAs

    cudaFuncSetAttribute(lstm2_kernel, cudaFuncAttributeMaxDynamicSharedMemorySize, SMEM_BYTES);
    lstm2_kernel<<<grid, NT, SMEM_BYTES>>>(x, W_ih0, W_hh0, b_ih0, b_hh0,
                                           W_ih1, W_hh1, b_ih1, b_hh1,
                                           W_fc, b_fc, out);
}

// round 5
// speedup vs baseline: 2.0692x; 2.0692x over previous
#include <cuda_runtime.h>

// LSTMModel: 2-layer LSTM (H=50), B=2048, T=512, input dim 1.
// Fused persistent kernel; one CTA per 16-batch tile; both layers per timestep.
// Matmuls: packed fma.rn.f32x2 over k-pairs. W stored in per-thread 16-float
// blocks padded to 20 floats (80B stride = 5 quad-banks, odd -> conflict-free
// LDS.128 across each 8-thread phase).

#define Hh 50
#define G4 200          // 4*H
#define GP 224          // padded gate dim (56 quads)
#define BT 16           // batch tile per CTA
#define NT 224          // threads (4 b-groups x 56 g-quads)
#define TT 512          // timesteps
#define HCS 104         // hc row stride: 0..49 h0, 50..99 h1, pad(0) 100..103
#define NC0 13          // k-chunks layer0 (covers k=0..51, zero-padded)
#define NC1 25          // k-chunks layer1 (k=0..99)
#define BLK 20          // floats per (chunk,thread) W block (16 data + 4 pad)

typedef unsigned long long ull;

// shared layout (floats; all offsets multiples of 4 -> 16B aligned)
#define SM_W0    0
#define SM_W1    (SM_W0 + NC0*56*BLK)     // 14560
#define SM_GATES (SM_W1 + NC1*56*BLK)     // +28000 = 42560
#define SM_HC    (SM_GATES + BT*GP)       // +3584
#define SM_B0    (SM_HC + BT*HCS)         // +1664
#define SM_B1    (SM_B0 + GP)
#define SM_WIH0  (SM_B1 + GP)
#define SM_FLOATS (SM_WIH0 + GP)
#define SMEM_BYTES (SM_FLOATS * sizeof(float))   // ~194 KB

__device__ __forceinline__ void ffma2(ull& d, ull a, ull b) {
    asm("fma.rn.f32x2 %0, %1, %2, %0;" : "+l"(d) : "l"(a), "l"(b));
}
__device__ __forceinline__ void unpack2(ull v, float& lo, float& hi) {
    asm("mov.b64 {%0, %1}, %2;" : "=f"(lo), "=f"(hi) : "l"(v));
}

__device__ __forceinline__ float sigf(float x) {
    float e = __expf(-x);
    return __fdividef(1.0f, 1.0f + e);
}
__device__ __forceinline__ float tanhf_fast(float x) {
    float e = __expf(2.0f * x);
    return 1.0f - __fdividef(2.0f, e + 1.0f);
}

__global__ __launch_bounds__(NT, 1)
void lstm2_kernel(const float* __restrict__ x,
                  const float* __restrict__ W_ih0, const float* __restrict__ W_hh0,
                  const float* __restrict__ b_ih0, const float* __restrict__ b_hh0,
                  const float* __restrict__ W_ih1, const float* __restrict__ W_hh1,
                  const float* __restrict__ b_ih1, const float* __restrict__ b_hh1,
                  const float* __restrict__ W_fc,  const float* __restrict__ b_fc,
                  float* __restrict__ out)
{
    extern __shared__ float sm[];
    float* W0    = sm + SM_W0;     // [NC0][56][BLK]
    float* W1    = sm + SM_W1;     // [NC1][56][BLK]
    float* gates = sm + SM_GATES;  // [BT][GP]
    float* hc    = sm + SM_HC;     // [BT][HCS]
    float* bias0 = sm + SM_B0;
    float* bias1 = sm + SM_B1;
    float* wih0  = sm + SM_WIH0;

    const int tid = threadIdx.x;

    // ---- one-time: blocked weight layout ----
    // W0 block (c,qq): 16 floats = W_hh0[4qq+gg][4c+kk], gg,kk in 0..3
    for (int i = tid; i < NC0 * 56 * BLK; i += NT) {
        int blk = i / BLK, r = i - blk * BLK;
        int c = blk / 56, qq = blk - c * 56;
        float v = 0.0f;
        if (r < 16) {
            int gg = r >> 2, kk = r & 3;
            int g = 4 * qq + gg, k = 4 * c + kk;
            if (g < G4 && k < Hh) v = W_hh0[g * Hh + k];
        }
        W0[i] = v;
    }
    // W1 block: concat [W_ih1; W_hh1] along k (K=100)
    for (int i = tid; i < NC1 * 56 * BLK; i += NT) {
        int blk = i / BLK, r = i - blk * BLK;
        int c = blk / 56, qq = blk - c * 56;
        float v = 0.0f;
        if (r < 16) {
            int gg = r >> 2, kk = r & 3;
            int g = 4 * qq + gg, k = 4 * c + kk;
            if (g < G4) v = (k < Hh) ? W_ih1[g * Hh + k] : W_hh1[g * Hh + (k - Hh)];
        }
        W1[i] = v;
    }
    for (int g = tid; g < GP; g += NT) {
        bias0[g] = (g < G4) ? (b_ih0[g] + b_hh0[g]) : 0.0f;
        bias1[g] = (g < G4) ? (b_ih1[g] + b_hh1[g]) : 0.0f;
        wih0[g]  = (g < G4) ? W_ih0[g] : 0.0f;
    }
    for (int i = tid; i < BT * HCS; i += NT) hc[i] = 0.0f;
    __syncthreads();

    // ---- thread tiling: 4 b's x 4 consecutive g's ----
    const int bg = tid / 56;          // 0..3
    const int q  = tid - bg * 56;     // 0..55
    const int g0 = q * 4;
    const int bbase = bg * 4;

    const float* hb0 = hc + (bbase + 0) * HCS;
    const float* hb1 = hc + (bbase + 1) * HCS;
    const float* hb2 = hc + (bbase + 2) * HCS;
    const float* hb3 = hc + (bbase + 3) * HCS;

    float c0r[4] = {0.f, 0.f, 0.f, 0.f};
    float c1r[4] = {0.f, 0.f, 0.f, 0.f};

    const float* xrow = x + (size_t)(blockIdx.x) * BT * TT;

    const float bv00 = bias0[g0], bv01 = bias0[g0+1], bv02 = bias0[g0+2], bv03 = bias0[g0+3];
    const float bv10 = bias1[g0], bv11 = bias1[g0+1], bv12 = bias1[g0+2], bv13 = bias1[g0+3];
    const float wi0 = wih0[g0], wi1 = wih0[g0+1], wi2 = wih0[g0+2], wi3 = wih0[g0+3];

    const float* w0base = W0 + q * BLK;   // + c*56*BLK per chunk
    const float* w1base = W1 + q * BLK;

    for (int t = 0; t < TT; ++t) {
        // ===== matmul A: gates0 = bias0 + x*W_ih0 + h0 @ W_hh0^T (K=50, 13 chunks) =====
        ull a[4][4];
        #pragma unroll
        for (int bb = 0; bb < 4; ++bb)
            #pragma unroll
            for (int gg = 0; gg < 4; ++gg) a[bb][gg] = 0ull;

        #pragma unroll 2
        for (int c = 0; c < NC0; ++c) {
            const float* wb = w0base + c * (56 * BLK);
            // 4 gates x 4 k, each float4 = one gate's k-quad = 2 packed k-pairs
            ulonglong2 wg0 = *(const ulonglong2*)(wb + 0);
            ulonglong2 wg1 = *(const ulonglong2*)(wb + 4);
            ulonglong2 wg2 = *(const ulonglong2*)(wb + 8);
            ulonglong2 wg3 = *(const ulonglong2*)(wb + 12);
            int kc = 4 * c;
            ull h[4][2];
            h[0][0] = *(const ull*)(hb0 + kc); h[0][1] = *(const ull*)(hb0 + kc + 2);
            h[1][0] = *(const ull*)(hb1 + kc); h[1][1] = *(const ull*)(hb1 + kc + 2);
            h[2][0] = *(const ull*)(hb2 + kc); h[2][1] = *(const ull*)(hb2 + kc + 2);
            h[3][0] = *(const ull*)(hb3 + kc); h[3][1] = *(const ull*)(hb3 + kc + 2);
            #pragma unroll
            for (int bb = 0; bb < 4; ++bb) {
                ffma2(a[bb][0], wg0.x, h[bb][0]); ffma2(a[bb][0], wg0.y, h[bb][1]);
                ffma2(a[bb][1], wg1.x, h[bb][0]); ffma2(a[bb][1], wg1.y, h[bb][1]);
                ffma2(a[bb][2], wg2.x, h[bb][0]); ffma2(a[bb][2], wg2.y, h[bb][1]);
                ffma2(a[bb][3], wg3.x, h[bb][0]); ffma2(a[bb][3], wg3.y, h[bb][1]);
            }
        }
        {
            float xv[4];
            xv[0] = __ldg(xrow + (bbase + 0) * TT + t);
            xv[1] = __ldg(xrow + (bbase + 1) * TT + t);
            xv[2] = __ldg(xrow + (bbase + 2) * TT + t);
            xv[3] = __ldg(xrow + (bbase + 3) * TT + t);
            const float bia[4] = {bv00, bv01, bv02, bv03};
            const float wiv[4] = {wi0, wi1, wi2, wi3};
            #pragma unroll
            for (int bb = 0; bb < 4; ++bb) {
                float v[4];
                #pragma unroll
                for (int gg = 0; gg < 4; ++gg) {
                    float lo, hi; unpack2(a[bb][gg], lo, hi);
                    v[gg] = fmaf(xv[bb], wiv[gg], bia[gg]) + (lo + hi);
                }
                *(float4*)(gates + (bbase + bb) * GP + g0) = make_float4(v[0], v[1], v[2], v[3]);
            }
        }
        __syncthreads();

        // ===== nonlinearity layer 0 -> h0 (hc cols 0..49) =====
        #pragma unroll
        for (int r = 0; r < 4; ++r) {
            int p = tid + r * NT;
            if (p < BT * Hh) {
                int b = p / Hh, j = p - b * Hh;
                const float* gb = gates + b * GP;
                float iv = sigf(gb[j]);
                float fv = sigf(gb[j + Hh]);
                float gv = tanhf_fast(gb[j + 2 * Hh]);
                float ov = sigf(gb[j + 3 * Hh]);
                float c = fmaf(fv, c0r[r], iv * gv);
                c0r[r] = c;
                hc[b * HCS + j] = ov * tanhf_fast(c);
            }
        }
        __syncthreads();

        // ===== matmul B: gates1 = bias1 + [h0;h1] @ [W_ih1;W_hh1]^T (K=100, 25 chunks) =====
        ull bacc[4][4];
        #pragma unroll
        for (int bb = 0; bb < 4; ++bb)
            #pragma unroll
            for (int gg = 0; gg < 4; ++gg) bacc[bb][gg] = 0ull;

        #pragma unroll 2
        for (int c = 0; c < NC1; ++c) {
            const float* wb = w1base + c * (56 * BLK);
            ulonglong2 wg0 = *(const ulonglong2*)(wb + 0);
            ulonglong2 wg1 = *(const ulonglong2*)(wb + 4);
            ulonglong2 wg2 = *(const ulonglong2*)(wb + 8);
            ulonglong2 wg3 = *(const ulonglong2*)(wb + 12);
            int kc = 4 * c;
            ull h[4][2];
            h[0][0] = *(const ull*)(hb0 + kc); h[0][1] = *(const ull*)(hb0 + kc + 2);
            h[1][0] = *(const ull*)(hb1 + kc); h[1][1] = *(const ull*)(hb1 + kc + 2);
            h[2][0] = *(const ull*)(hb2 + kc); h[2][1] = *(const ull*)(hb2 + kc + 2);
            h[3][0] = *(const ull*)(hb3 + kc); h[3][1] = *(const ull*)(hb3 + kc + 2);
            #pragma unroll
            for (int bb = 0; bb < 4; ++bb) {
                ffma2(bacc[bb][0], wg0.x, h[bb][0]); ffma2(bacc[bb][0], wg0.y, h[bb][1]);
                ffma2(bacc[bb][1], wg1.x, h[bb][0]); ffma2(bacc[bb][1], wg1.y, h[bb][1]);
                ffma2(bacc[bb][2], wg2.x, h[bb][0]); ffma2(bacc[bb][2], wg2.y, h[bb][1]);
                ffma2(bacc[bb][3], wg3.x, h[bb][0]); ffma2(bacc[bb][3], wg3.y, h[bb][1]);
            }
        }
        {
            const float bia[4] = {bv10, bv11, bv12, bv13};
            #pragma unroll
            for (int bb = 0; bb < 4; ++bb) {
                float v[4];
                #pragma unroll
                for (int gg = 0; gg < 4; ++gg) {
                    float lo, hi; unpack2(bacc[bb][gg], lo, hi);
                    v[gg] = bia[gg] + (lo + hi);
                }
                *(float4*)(gates + (bbase + bb) * GP + g0) = make_float4(v[0], v[1], v[2], v[3]);
            }
        }
        __syncthreads();

        // ===== nonlinearity layer 1 -> h1 (hc cols 50..99) =====
        #pragma unroll
        for (int r = 0; r < 4; ++r) {
            int p = tid + r * NT;
            if (p < BT * Hh) {
                int b = p / Hh, j = p - b * Hh;
                const float* gb = gates + b * GP;
                float iv = sigf(gb[j]);
                float fv = sigf(gb[j + Hh]);
                float gv = tanhf_fast(gb[j + 2 * Hh]);
                float ov = sigf(gb[j + 3 * Hh]);
                float c = fmaf(fv, c1r[r], iv * gv);
                c1r[r] = c;
                hc[b * HCS + Hh + j] = ov * tanhf_fast(c);
            }
        }
        __syncthreads();
    }

    // ===== final FC: out[b] = h1[b] . W_fc + b_fc =====
    if (tid < BT) {
        float s = b_fc[0];
        const float* hrow = hc + tid * HCS + Hh;
        #pragma unroll
        for (int j = 0; j < Hh; ++j) s = fmaf(hrow[j], __ldg(W_fc + j), s);
        out[blockIdx.x * BT + tid] = s;
    }
}

extern "C" void kernel_launch(void* const* d_in, const int* in_sizes, int n_in,
                              void* d_out, int out_size)
{
    const float* x     = (const float*)d_in[0];
    const float* W_ih0 = (const float*)d_in[1];
    const float* W_hh0 = (const float*)d_in[2];
    const float* b_ih0 = (const float*)d_in[3];
    const float* b_hh0 = (const float*)d_in[4];
    const float* W_ih1 = (const float*)d_in[5];
    const float* W_hh1 = (const float*)d_in[6];
    const float* b_ih1 = (const float*)d_in[7];
    const float* b_hh1 = (const float*)d_in[8];
    const float* W_fc  = (const float*)d_in[9];
    const float* b_fc  = (const float*)d_in[10];
    float* out = (float*)d_out;

    int B = in_sizes[0] / TT;          // x is [B, T, 1]
    int grid = B / BT;                 // 128 CTAs

    cudaFuncSetAttribute(lstm2_kernel, cudaFuncAttributeMaxDynamicSharedMemorySize, SMEM_BYTES);
    lstm2_kernel<<<grid, NT, SMEM_BYTES>>>(x, W_ih0, W_hh0, b_ih0, b_hh0,
                                           W_ih1, W_hh1, b_ih1, b_hh1,
                                           W_fc, b_fc, out);
}